// round 4
// baseline (speedup 1.0000x reference)
#include <cuda_runtime.h>
#include <cstdint>

#define EPS   1e-9f
#define ITERS 20
#define LDK   68      // padded shared row stride in floats (17 float4)

typedef unsigned long long ull;

__device__ __forceinline__ ull pack2f(float lo, float hi) {
    ull r; asm("mov.b64 %0, {%1, %2};" : "=l"(r) : "f"(lo), "f"(hi)); return r;
}
__device__ __forceinline__ void unpack2f(ull p, float& lo, float& hi) {
    asm("mov.b64 {%0, %1}, %2;" : "=f"(lo), "=f"(hi) : "l"(p));
}
// packed 2xfp32 FMA / ADD — only reachable via PTX on sm_10x
__device__ __forceinline__ ull ffma2(ull a, ull b, ull c) {
    ull d; asm("fma.rn.f32x2 %0, %1, %2, %3;" : "=l"(d) : "l"(a), "l"(b), "l"(c)); return d;
}
__device__ __forceinline__ ull fadd2(ull a, ull b) {
    ull d; asm("add.rn.f32x2 %0, %1, %2;" : "=l"(d) : "l"(a), "l"(b)); return d;
}

// Dual dot product: da = dot(A, w), db = dot(B, w) where A,B are 32 packed
// f32x2 (64 floats) and w is a 64-float broadcast vector in shared memory.
// 8 independent FMA chains of depth 8; w loaded once (16 LDS.128), used twice.
__device__ __forceinline__ void dot2(const ull* A, const ull* B,
                                     const float* w, float& da, float& db)
{
    ull a0 = 0, a1 = 0, a2 = 0, a3 = 0;
    ull b0 = 0, b1 = 0, b2 = 0, b3 = 0;
    const float4* w4 = reinterpret_cast<const float4*>(w);
    #pragma unroll
    for (int j = 0; j < 4; j++) {
        float4 t0 = w4[4 * j + 0];
        float4 t1 = w4[4 * j + 1];
        float4 t2 = w4[4 * j + 2];
        float4 t3 = w4[4 * j + 3];
        ull w0 = pack2f(t0.x, t0.y), w1 = pack2f(t0.z, t0.w);
        ull w2 = pack2f(t1.x, t1.y), w3 = pack2f(t1.z, t1.w);
        ull w4_ = pack2f(t2.x, t2.y), w5 = pack2f(t2.z, t2.w);
        ull w6 = pack2f(t3.x, t3.y), w7 = pack2f(t3.z, t3.w);
        a0 = ffma2(A[8 * j + 0], w0, a0);
        a1 = ffma2(A[8 * j + 1], w1, a1);
        a2 = ffma2(A[8 * j + 2], w2, a2);
        a3 = ffma2(A[8 * j + 3], w3, a3);
        b0 = ffma2(B[8 * j + 0], w0, b0);
        b1 = ffma2(B[8 * j + 1], w1, b1);
        b2 = ffma2(B[8 * j + 2], w2, b2);
        b3 = ffma2(B[8 * j + 3], w3, b3);
        a0 = ffma2(A[8 * j + 4], w4_, a0);
        a1 = ffma2(A[8 * j + 5], w5, a1);
        a2 = ffma2(A[8 * j + 6], w6, a2);
        a3 = ffma2(A[8 * j + 7], w7, a3);
        b0 = ffma2(B[8 * j + 4], w4_, b0);
        b1 = ffma2(B[8 * j + 5], w5, b1);
        b2 = ffma2(B[8 * j + 6], w6, b2);
        b3 = ffma2(B[8 * j + 7], w7, b3);
    }
    ull sa = fadd2(fadd2(a0, a1), fadd2(a2, a3));
    ull sb = fadd2(fadd2(b0, b1), fadd2(b2, b3));
    float l, h;
    unpack2f(sa, l, h); da = l + h;
    unpack2f(sb, l, h); db = l + h;
}

__global__ __launch_bounds__(64)
void sinkhorn_kernel(const float* __restrict__ x, float* __restrict__ out)
{
    __shared__ __align__(16) float shK[64 * LDK];
    __shared__ __align__(16) float shv[64];
    __shared__ __align__(16) float shu[64];

    const int tid  = threadIdx.x;
    const int lane = tid & 31;
    const int warp = tid >> 5;
    const long long m = blockIdx.x;
    const float4* __restrict__ x4 = reinterpret_cast<const float4*>(x) + m * 1024;
    float4* __restrict__ o4       = reinterpret_cast<float4*>(out)     + m * 1024;

    // ---- coalesced load, exp, stage into padded shared -------------------
    #pragma unroll
    for (int j = 0; j < 16; j++) {
        int e4 = j * 64 + tid;            // float4 linear index within matrix
        float4 t = x4[e4];
        int row = e4 >> 4;
        int c4  = e4 & 15;
        float4 e;
        e.x = __expf(t.x); e.y = __expf(t.y);
        e.z = __expf(t.z); e.w = __expf(t.w);
        reinterpret_cast<float4*>(shK)[row * 17 + c4] = e;
    }
    shv[tid] = 1.0f;
    __syncthreads();

    // ---- gather: warp0 thread holds rows (2*lane, 2*lane+1)
    //              warp1 thread holds cols (2*lane, 2*lane+1) --------------
    ull A[32], B[32];       // 64 packed f32x2 = 128 regs of K data
    if (warp == 0) {
        const int r0 = 2 * lane, r1 = 2 * lane + 1;
        #pragma unroll
        for (int j = 0; j < 16; j++) {
            float4 t = reinterpret_cast<const float4*>(shK)[r0 * 17 + j];
            A[2 * j]     = pack2f(t.x, t.y);
            A[2 * j + 1] = pack2f(t.z, t.w);
            float4 s = reinterpret_cast<const float4*>(shK)[r1 * 17 + j];
            B[2 * j]     = pack2f(s.x, s.y);
            B[2 * j + 1] = pack2f(s.z, s.w);
        }
    } else {
        const int c0 = 2 * lane, c1 = 2 * lane + 1;
        #pragma unroll
        for (int j = 0; j < 32; j++) {
            A[j] = pack2f(shK[(2 * j) * LDK + c0], shK[(2 * j + 1) * LDK + c0]);
            B[j] = pack2f(shK[(2 * j) * LDK + c1], shK[(2 * j + 1) * LDK + c1]);
        }
    }

    float p0 = 1.0f, p1 = 1.0f;   // warp0: (u_{2l}, u_{2l+1}); warp1: (v_{2l}, v_{2l+1})

    #pragma unroll 1
    for (int it = 0; it < ITERS; it++) {
        if (warp == 0) {
            // row step: u' = u / (u * (K v) + eps)
            float da, db;
            dot2(A, B, shv, da, db);
            p0 = __fdividef(p0, fmaf(p0, da, EPS));
            p1 = __fdividef(p1, fmaf(p1, db, EPS));
            reinterpret_cast<float2*>(shu)[lane] = make_float2(p0, p1);
        }
        __syncthreads();
        if (warp == 1) {
            // col step: v' = v / (v * (K^T u') + eps)
            float da, db;
            dot2(A, B, shu, da, db);
            p0 = __fdividef(p0, fmaf(p0, da, EPS));
            p1 = __fdividef(p1, fmaf(p1, db, EPS));
            reinterpret_cast<float2*>(shv)[lane] = make_float2(p0, p1);
        }
        __syncthreads();
    }

    // ---- output M = diag(u) K diag(v): warp0 stages its 2 rows ----------
    if (warp == 0) {
        const int r0 = 2 * lane, r1 = 2 * lane + 1;
        #pragma unroll
        for (int j = 0; j < 16; j++) {
            float4 vv = reinterpret_cast<const float4*>(shv)[j];
            float k0, k1, k2, k3;
            unpack2f(A[2 * j],     k0, k1);
            unpack2f(A[2 * j + 1], k2, k3);
            float4 r;
            r.x = p0 * k0 * vv.x; r.y = p0 * k1 * vv.y;
            r.z = p0 * k2 * vv.z; r.w = p0 * k3 * vv.w;
            reinterpret_cast<float4*>(shK)[r0 * 17 + j] = r;
            unpack2f(B[2 * j],     k0, k1);
            unpack2f(B[2 * j + 1], k2, k3);
            float4 s;
            s.x = p1 * k0 * vv.x; s.y = p1 * k1 * vv.y;
            s.z = p1 * k2 * vv.z; s.w = p1 * k3 * vv.w;
            reinterpret_cast<float4*>(shK)[r1 * 17 + j] = s;
        }
    }
    __syncthreads();

    // ---- coalesced copy-out ---------------------------------------------
    #pragma unroll
    for (int j = 0; j < 16; j++) {
        int e4 = j * 64 + tid;
        int row = e4 >> 4;
        int c4  = e4 & 15;
        o4[e4] = reinterpret_cast<const float4*>(shK)[row * 17 + c4];
    }
}

extern "C" void kernel_launch(void* const* d_in, const int* in_sizes, int n_in,
                              void* d_out, int out_size)
{
    const float* x = (const float*)d_in[0];
    float* out = (float*)d_out;
    int nmat = in_sizes[0] / 4096;   // 64*64 elements per matrix
    sinkhorn_kernel<<<nmat, 64>>>(x, out);
}